// round 1
// baseline (speedup 1.0000x reference)
#include <cuda_runtime.h>
#include <math.h>

#define B_SZ   4
#define L_SEQ  2048
#define DMODEL 1024
#define DINNER 2048
#define DSTATE 16

// ---------------- scratch (device globals: allowed scratch mechanism) --------
__device__ float g_xz   [(size_t)B_SZ * L_SEQ * 2 * DINNER];  // in_proj out (u|z)
__device__ float g_uact [(size_t)B_SZ * L_SEQ * DINNER];      // conv+silu out
__device__ float g_xdbl [(size_t)B_SZ * L_SEQ * 96];          // x_proj out
__device__ float g_delta[(size_t)B_SZ * L_SEQ * DINNER];      // softplus(dt)
__device__ float g_yv   [(size_t)B_SZ * L_SEQ * DINNER];      // scan output (gated)
__device__ float g_o1   [(size_t)B_SZ * L_SEQ * DMODEL];
__device__ float g_o2   [(size_t)B_SZ * L_SEQ * DMODEL];

// ---------------- generic tiled SGEMM: C = A * B^T (+bias)(+softplus) --------
// A: if ACOL, A[m,k] = A[k*lda + m] (column-major view, used for x input)
//    else      A[m,k] = A[m*lda + k] (row-major)
// B: weights, row-major N x K: B[n,k] = B[n*ldb + k]
// C: row-major, ldc.   ACT: 0=none, 1=+bias, 2=+bias then softplus.
// No bounds guards: all M%BM==0, N%BN==0, K%BK==0 by construction.
template<int BM,int BN,int BK,int TM,int TN,bool ACOL,int ACT>
__global__ void __launch_bounds__(256)
gemm_k(const float* __restrict__ A, const float* __restrict__ Bw,
       const float* __restrict__ bias, float* __restrict__ C,
       int K, int lda, int ldb, int ldc, long sA, long sC)
{
    __shared__ float As[BK][BM + 4];   // +4 keeps rows 16B-aligned & conflict-free
    __shared__ float Bs[BK][BN + 4];
    const int tid = threadIdx.x;
    const float* Ab = A + (long)blockIdx.z * sA;
    float* Cb       = C + (long)blockIdx.z * sC;
    const int m0 = blockIdx.y * BM;
    const int n0 = blockIdx.x * BN;
    const int tx = tid % (BN / TN);
    const int ty = tid / (BN / TN);

    float acc[TM][TN];
#pragma unroll
    for (int i = 0; i < TM; i++)
#pragma unroll
        for (int j = 0; j < TN; j++) acc[i][j] = 0.f;

    for (int k0 = 0; k0 < K; k0 += BK) {
#pragma unroll
        for (int i = tid; i < BM * BK; i += 256) {
            int m, k;
            if (ACOL) { m = i % BM; k = i / BM; }   // m fastest -> coalesced for col-major
            else      { k = i % BK; m = i / BK; }   // k fastest -> coalesced for row-major
            float v = ACOL ? Ab[(long)(k0 + k) * lda + (m0 + m)]
                           : Ab[(long)(m0 + m) * lda + (k0 + k)];
            As[k][m] = v;
        }
#pragma unroll
        for (int i = tid; i < BN * BK; i += 256) {
            int k = i % BK, n = i / BK;
            Bs[k][n] = Bw[(long)(n0 + n) * ldb + (k0 + k)];
        }
        __syncthreads();
#pragma unroll
        for (int kk = 0; kk < BK; kk++) {
            float a[TM], b[TN];
#pragma unroll
            for (int i = 0; i < TM; i++) a[i] = As[kk][ty * TM + i];
#pragma unroll
            for (int j = 0; j < TN; j++) b[j] = Bs[kk][tx * TN + j];
#pragma unroll
            for (int i = 0; i < TM; i++)
#pragma unroll
                for (int j = 0; j < TN; j++)
                    acc[i][j] = fmaf(a[i], b[j], acc[i][j]);
        }
        __syncthreads();
    }

#pragma unroll
    for (int i = 0; i < TM; i++) {
        int m = m0 + ty * TM + i;
#pragma unroll
        for (int j = 0; j < TN; j++) {
            int n = n0 + tx * TN + j;
            float v = acc[i][j];
            if (ACT >= 1) v += bias[n];
            if (ACT == 2) v = (v > 20.f) ? v : log1pf(__expf(v));
            Cb[(long)m * ldc + n] = v;
        }
    }
}

// ---------------- depthwise causal conv(4) + SiLU ----------------------------
__global__ void __launch_bounds__(256)
conv_silu_k(const float* __restrict__ cw, const float* __restrict__ cb)
{
    long idx = (long)blockIdx.x * 256 + threadIdx.x;   // over B*L*DINNER
    int  e  = (int)(idx % DINNER);
    long bl = idx / DINNER;
    int  l  = (int)(bl % L_SEQ);
    long brow = bl - l;                                 // b * L
    float acc = cb[e];
#pragma unroll
    for (int k = 0; k < 4; k++) {
        int t = l - 3 + k;
        if (t >= 0)
            acc = fmaf(cw[e * 4 + k], g_xz[(brow + t) * (2 * DINNER) + e], acc);
    }
    g_uact[idx] = acc / (1.f + __expf(-acc));           // silu
}

// ---------------- selective scan: 16 lanes per (b,d) channel -----------------
// Also fuses the D-skip and the silu(z) gate: y = (scan + u*D) * silu(z)
__global__ void __launch_bounds__(256)
scan_k(const float* __restrict__ A_log, const float* __restrict__ Dp)
{
    const int b  = blockIdx.x >> 7;          // / (DINNER/16)
    const int dg = blockIdx.x & 127;
    const int ci = threadIdx.x >> 4;
    const int n  = threadIdx.x & 15;
    const int d  = dg * 16 + ci;

    const float Av = -expf(A_log[d * DSTATE + n]);
    const float Dv = Dp[d];

    long i2048 = ((long)b * L_SEQ) * DINNER + d;
    long i4096 = ((long)b * L_SEQ) * (2 * DINNER) + DINNER + d;  // z half
    long i96   = ((long)b * L_SEQ) * 96;

    float h  = 0.f;
    float dv = g_delta[i2048];
    float uv = g_uact[i2048];
    float zv = g_xz[i4096];
    float Bv = g_xdbl[i96 + 64 + n];
    float Cv = g_xdbl[i96 + 80 + n];

    for (int l = 0; l < L_SEQ; l++) {
        float dv2 = 0.f, uv2 = 0.f, zv2 = 0.f, Bv2 = 0.f, Cv2 = 0.f;
        if (l + 1 < L_SEQ) {                   // prefetch next step (hides latency)
            dv2 = g_delta[i2048 + DINNER];
            uv2 = g_uact [i2048 + DINNER];
            zv2 = g_xz   [i4096 + 2 * DINNER];
            Bv2 = g_xdbl [i96 + 96 + 64 + n];
            Cv2 = g_xdbl [i96 + 96 + 80 + n];
        }
        float dA = __expf(dv * Av);
        h = fmaf(dA, h, dv * Bv * uv);
        float p = h * Cv;
        p += __shfl_xor_sync(0xffffffffu, p, 8, 16);
        p += __shfl_xor_sync(0xffffffffu, p, 4, 16);
        p += __shfl_xor_sync(0xffffffffu, p, 2, 16);
        p += __shfl_xor_sync(0xffffffffu, p, 1, 16);
        if (n == 0) {
            float sil = zv / (1.f + __expf(-zv));
            g_yv[i2048] = (p + uv * Dv) * sil;
        }
        dv = dv2; uv = uv2; zv = zv2; Bv = Bv2; Cv = Cv2;
        i2048 += DINNER; i4096 += 2 * DINNER; i96 += 96;
    }
}

// ---------------- final transpose: [b][l][m] -> [b][m][l] --------------------
__global__ void transpose_k(float* __restrict__ out)
{
    __shared__ float tile[32][33];
    const int b  = blockIdx.z;
    const int m0 = blockIdx.x * 32;
    const int l0 = blockIdx.y * 32;
#pragma unroll
    for (int r = threadIdx.y; r < 32; r += 8)
        tile[r][threadIdx.x] =
            g_o2[((long)b * L_SEQ + l0 + r) * DMODEL + m0 + threadIdx.x];
    __syncthreads();
#pragma unroll
    for (int r = threadIdx.y; r < 32; r += 8)
        out[((long)b * DMODEL + m0 + r) * L_SEQ + l0 + threadIdx.x] =
            tile[threadIdx.x][r];
}

// ---------------- host launcher ----------------------------------------------
extern "C" void kernel_launch(void* const* d_in, const int* in_sizes, int n_in,
                              void* d_out, int out_size)
{
    (void)in_sizes; (void)n_in; (void)out_size;
    const float* x      = (const float*)d_in[0];   // (B, d_model, L)
    const float* w_in   = (const float*)d_in[1];   // (4096, 1024)
    const float* conv_w = (const float*)d_in[2];   // (2048, 4)
    const float* conv_b = (const float*)d_in[3];   // (2048,)
    const float* w_x    = (const float*)d_in[4];   // (96, 2048)
    const float* w_dt   = (const float*)d_in[5];   // (2048, 64)
    const float* b_dt   = (const float*)d_in[6];   // (2048,)
    const float* A_log  = (const float*)d_in[7];   // (2048, 16)
    const float* Dp     = (const float*)d_in[8];   // (2048,)
    const float* w_out  = (const float*)d_in[9];   // (1024, 2048)
    const float* w_p    = (const float*)d_in[10];  // (1024, 1024)
    const float* b_p    = (const float*)d_in[11];  // (1024,)
    float* out = (float*)d_out;

    float *xz, *uact, *xdbl, *delta, *yv, *o1, *o2;
    cudaGetSymbolAddress((void**)&xz,    g_xz);
    cudaGetSymbolAddress((void**)&uact,  g_uact);
    cudaGetSymbolAddress((void**)&xdbl,  g_xdbl);
    cudaGetSymbolAddress((void**)&delta, g_delta);
    cudaGetSymbolAddress((void**)&yv,    g_yv);
    cudaGetSymbolAddress((void**)&o1,    g_o1);
    cudaGetSymbolAddress((void**)&o2,    g_o2);

    // 1) in_proj: xz[b][l][e] = sum_d x[b][d][l] * w_in[e][d]   (A col-major)
    gemm_k<128,128,8,8,8,true,0><<<dim3((2*DINNER)/128, L_SEQ/128, B_SZ), 256>>>(
        x, w_in, nullptr, xz,
        DMODEL, /*lda=*/L_SEQ, /*ldb=*/DMODEL, /*ldc=*/2*DINNER,
        (long)DMODEL * L_SEQ, (long)L_SEQ * 2 * DINNER);

    // 2) depthwise causal conv + silu -> uact
    conv_silu_k<<<(B_SZ * L_SEQ * DINNER) / 256, 256>>>(conv_w, conv_b);

    // 3) x_proj: xdbl[m][0..95] = uact @ w_x^T   (skinny N=96)
    gemm_k<32,96,8,2,6,false,0><<<dim3(1, (B_SZ * L_SEQ) / 32), 256>>>(
        uact, w_x, nullptr, xdbl,
        DINNER, /*lda=*/DINNER, /*ldb=*/DINNER, /*ldc=*/96, 0, 0);

    // 4) delta = softplus(xdbl[:, :64] @ w_dt^T + b_dt)
    gemm_k<128,128,8,8,8,false,2><<<dim3(DINNER/128, (B_SZ * L_SEQ) / 128), 256>>>(
        xdbl, w_dt, b_dt, delta,
        64, /*lda=*/96, /*ldb=*/64, /*ldc=*/DINNER, 0, 0);

    // 5) selective scan (fuses D-skip and silu(z) gate) -> yv
    scan_k<<<B_SZ * (DINNER / 16), 256>>>(A_log, Dp);

    // 6) out_proj: o1 = yv @ w_out^T
    gemm_k<128,128,8,8,8,false,0><<<dim3(DMODEL/128, (B_SZ * L_SEQ) / 128), 256>>>(
        yv, w_out, nullptr, o1,
        DINNER, /*lda=*/DINNER, /*ldb=*/DINNER, /*ldc=*/DMODEL, 0, 0);

    // 7) proj: o2 = o1 @ w_p^T + b_p
    gemm_k<128,128,8,8,8,false,1><<<dim3(DMODEL/128, (B_SZ * L_SEQ) / 128), 256>>>(
        o1, w_p, b_p, o2,
        DMODEL, /*lda=*/DMODEL, /*ldb=*/DMODEL, /*ldc=*/DMODEL, 0, 0);

    // 8) transpose to (B, d_model, L)
    transpose_k<<<dim3(DMODEL/32, L_SEQ/32, B_SZ), dim3(32, 8)>>>(out);
}

// round 2
// speedup vs baseline: 1.9514x; 1.9514x over previous
#include <cuda_runtime.h>
#include <math.h>
#include <stdint.h>

#define B_SZ   4
#define L_SEQ  2048
#define DMODEL 1024
#define DINNER 2048
#define DSTATE 16
#define MTOT   (B_SZ * L_SEQ)   // 8192

// ---------------- scratch ----------------------------------------------------
__device__ float g_xt   [(size_t)MTOT * DMODEL];        // x transposed (b,l,d)
__device__ float g_xz   [(size_t)MTOT * 2 * DINNER];    // in_proj out (u|z)
__device__ float g_uact [(size_t)MTOT * DINNER];        // conv+silu out
__device__ float g_xdbl [(size_t)MTOT * 96];            // x_proj out
__device__ float g_delta[(size_t)MTOT * DINNER];        // softplus(dt)
__device__ float g_yv   [(size_t)MTOT * DINNER];        // scan output (gated)
__device__ float g_o1   [(size_t)MTOT * DMODEL];
__device__ float g_o2   [(size_t)MTOT * DMODEL];

// ---------------- tf32 tensor-core GEMM: C = A @ W^T (+bias)(+softplus) ------
// A: row-major [M, lda]; W: row-major [N, ldb] (so C[m,n] = sum_k A[m,k]W[n,k])
// BM=BN=128, BK=16. 256 threads = 8 warps, warp tile 64x32 (m16n8k8 x 4x4).
__device__ __forceinline__ uint32_t f2tf32(float f) {
    uint32_t r;
    asm("cvt.rna.tf32.f32 %0, %1;" : "=r"(r) : "f"(f));
    return r;
}

#define MMA_TF32(c, a, b)                                             \
    asm volatile(                                                     \
        "mma.sync.aligned.m16n8k8.row.col.f32.tf32.tf32.f32 "         \
        "{%0,%1,%2,%3}, {%4,%5,%6,%7}, {%8,%9}, {%0,%1,%2,%3};\n"     \
        : "+f"(c[0]), "+f"(c[1]), "+f"(c[2]), "+f"(c[3])              \
        : "r"(a[0]), "r"(a[1]), "r"(a[2]), "r"(a[3]),                 \
          "r"(b[0]), "r"(b[1]))

template<int ACT, bool NGUARD>
__global__ void __launch_bounds__(256)
tgemm(const float* __restrict__ A, const float* __restrict__ W,
      const float* __restrict__ bias, float* __restrict__ C,
      int K, int lda, int ldb, int ldc, int Nt)
{
    __shared__ uint32_t As[2][128 * 20];   // [m][k] pitch 20 -> conflict-free frags
    __shared__ uint32_t Bs[2][128 * 20];   // [n][k] pitch 20

    const int tid  = threadIdx.x;
    const int wid  = tid >> 5;
    const int lane = tid & 31;
    const int m0   = blockIdx.y * 128;
    const int n0   = blockIdx.x * 128;
    const int wm   = (wid & 1) * 64;
    const int wn   = (wid >> 1) * 32;
    const int gid  = lane >> 2;
    const int tig  = lane & 3;

    const int lr = tid >> 2;        // 0..63 (row within half-tile)
    const int lk = (tid & 3) * 4;   // 0,4,8,12 (k offset, float4)

    const float* Ap0 = A + (long)(m0 + lr) * lda + lk;
    const float* Ap1 = Ap0 + (long)64 * lda;
    const bool bok0 = !NGUARD || (n0 + lr)      < Nt;
    const bool bok1 = !NGUARD || (n0 + lr + 64) < Nt;
    const float* Bp0 = W + (long)(n0 + lr) * ldb + lk;
    const float* Bp1 = Bp0 + (long)64 * ldb;

    float acc[4][4][4];
#pragma unroll
    for (int i = 0; i < 4; i++)
#pragma unroll
        for (int j = 0; j < 4; j++)
#pragma unroll
            for (int q = 0; q < 4; q++) acc[i][j][q] = 0.f;

    float4 ra0, ra1, rb0, rb1;
    const float4 z4 = make_float4(0.f, 0.f, 0.f, 0.f);

#define FETCH(k0)                                                      \
    do {                                                               \
        ra0 = *(const float4*)(Ap0 + (k0));                            \
        ra1 = *(const float4*)(Ap1 + (k0));                            \
        rb0 = bok0 ? *(const float4*)(Bp0 + (k0)) : z4;                \
        rb1 = bok1 ? *(const float4*)(Bp1 + (k0)) : z4;                \
    } while (0)

#define STORE(buf)                                                     \
    do {                                                               \
        uint32_t* pa0 = &As[buf][lr * 20 + lk];                        \
        uint32_t* pa1 = &As[buf][(lr + 64) * 20 + lk];                 \
        uint32_t* pb0 = &Bs[buf][lr * 20 + lk];                        \
        uint32_t* pb1 = &Bs[buf][(lr + 64) * 20 + lk];                 \
        pa0[0] = f2tf32(ra0.x); pa0[1] = f2tf32(ra0.y);                \
        pa0[2] = f2tf32(ra0.z); pa0[3] = f2tf32(ra0.w);                \
        pa1[0] = f2tf32(ra1.x); pa1[1] = f2tf32(ra1.y);                \
        pa1[2] = f2tf32(ra1.z); pa1[3] = f2tf32(ra1.w);                \
        pb0[0] = f2tf32(rb0.x); pb0[1] = f2tf32(rb0.y);                \
        pb0[2] = f2tf32(rb0.z); pb0[3] = f2tf32(rb0.w);                \
        pb1[0] = f2tf32(rb1.x); pb1[1] = f2tf32(rb1.y);                \
        pb1[2] = f2tf32(rb1.z); pb1[3] = f2tf32(rb1.w);                \
    } while (0)

    FETCH(0);
    STORE(0);
    __syncthreads();

    const int nk = K / 16;
    for (int kt = 0; kt < nk; kt++) {
        const int buf = kt & 1;
        if (kt + 1 < nk) FETCH((kt + 1) * 16);

#pragma unroll
        for (int ks = 0; ks < 2; ks++) {
            const int kb = ks * 8 + tig;
            uint32_t af[4][4], bf[4][2];
#pragma unroll
            for (int mi = 0; mi < 4; mi++) {
                const uint32_t* p = &As[buf][(wm + mi * 16 + gid) * 20 + kb];
                af[mi][0] = p[0];
                af[mi][1] = p[8 * 20];
                af[mi][2] = p[4];
                af[mi][3] = p[8 * 20 + 4];
            }
#pragma unroll
            for (int ni = 0; ni < 4; ni++) {
                const uint32_t* p = &Bs[buf][(wn + ni * 8 + gid) * 20 + kb];
                bf[ni][0] = p[0];
                bf[ni][1] = p[4];
            }
#pragma unroll
            for (int mi = 0; mi < 4; mi++)
#pragma unroll
                for (int ni = 0; ni < 4; ni++)
                    MMA_TF32(acc[mi][ni], af[mi], bf[ni]);
        }

        if (kt + 1 < nk) STORE(buf ^ 1);
        __syncthreads();
    }

    // epilogue
#pragma unroll
    for (int mi = 0; mi < 4; mi++) {
        const int r0 = m0 + wm + mi * 16 + gid;
        const int r1 = r0 + 8;
#pragma unroll
        for (int ni = 0; ni < 4; ni++) {
            const int cn = n0 + wn + ni * 8 + tig * 2;
            if (NGUARD && cn >= Nt) continue;
            float v0 = acc[mi][ni][0], v1 = acc[mi][ni][1];
            float v2 = acc[mi][ni][2], v3 = acc[mi][ni][3];
            if (ACT >= 1) {
                const float b0 = bias[cn], b1 = bias[cn + 1];
                v0 += b0; v1 += b1; v2 += b0; v3 += b1;
            }
            if (ACT == 2) {
                v0 = (v0 > 20.f) ? v0 : log1pf(__expf(v0));
                v1 = (v1 > 20.f) ? v1 : log1pf(__expf(v1));
                v2 = (v2 > 20.f) ? v2 : log1pf(__expf(v2));
                v3 = (v3 > 20.f) ? v3 : log1pf(__expf(v3));
            }
            C[(long)r0 * ldc + cn]     = v0;
            C[(long)r0 * ldc + cn + 1] = v1;
            C[(long)r1 * ldc + cn]     = v2;
            C[(long)r1 * ldc + cn + 1] = v3;
        }
    }
#undef FETCH
#undef STORE
}

// ---------------- generic 32x32 tiled transpose: dst[z][c][r] = src[z][r][c] -
__global__ void transpose_k(const float* __restrict__ src, float* __restrict__ dst,
                            int R, int Cc)
{
    __shared__ float t[32][33];
    const long zoff = (long)blockIdx.z * R * Cc;
    const float* s = src + zoff;
    float* d = dst + zoff;
    const int r0 = blockIdx.y * 32, c0 = blockIdx.x * 32;
#pragma unroll
    for (int i = threadIdx.y; i < 32; i += 8)
        t[i][threadIdx.x] = s[(long)(r0 + i) * Cc + c0 + threadIdx.x];
    __syncthreads();
#pragma unroll
    for (int i = threadIdx.y; i < 32; i += 8)
        d[(long)(c0 + i) * R + r0 + threadIdx.x] = t[threadIdx.x][i];
}

// ---------------- depthwise causal conv(4) + SiLU ----------------------------
__global__ void __launch_bounds__(256)
conv_silu_k(const float* __restrict__ cw, const float* __restrict__ cb)
{
    long idx = (long)blockIdx.x * 256 + threadIdx.x;   // over B*L*DINNER
    int  e  = (int)(idx % DINNER);
    long bl = idx / DINNER;
    int  l  = (int)(bl % L_SEQ);
    long brow = bl - l;                                 // b * L
    float acc = cb[e];
#pragma unroll
    for (int k = 0; k < 4; k++) {
        int t = l - 3 + k;
        if (t >= 0)
            acc = fmaf(cw[e * 4 + k], g_xz[(brow + t) * (2 * DINNER) + e], acc);
    }
    g_uact[idx] = acc / (1.f + __expf(-acc));           // silu
}

// ---------------- selective scan: 16 lanes per (b,d) channel -----------------
__global__ void __launch_bounds__(256)
scan_k(const float* __restrict__ A_log, const float* __restrict__ Dp)
{
    const int b  = blockIdx.x >> 7;
    const int dg = blockIdx.x & 127;
    const int ci = threadIdx.x >> 4;
    const int n  = threadIdx.x & 15;
    const int d  = dg * 16 + ci;

    const float Av = -expf(A_log[d * DSTATE + n]);
    const float Dv = Dp[d];

    long i2048 = ((long)b * L_SEQ) * DINNER + d;
    long i4096 = ((long)b * L_SEQ) * (2 * DINNER) + DINNER + d;
    long i96   = ((long)b * L_SEQ) * 96;

    float h  = 0.f;
    float dv = g_delta[i2048];
    float uv = g_uact[i2048];
    float zv = g_xz[i4096];
    float Bv = g_xdbl[i96 + 64 + n];
    float Cv = g_xdbl[i96 + 80 + n];

    for (int l = 0; l < L_SEQ; l++) {
        float dv2 = 0.f, uv2 = 0.f, zv2 = 0.f, Bv2 = 0.f, Cv2 = 0.f;
        if (l + 1 < L_SEQ) {
            dv2 = g_delta[i2048 + DINNER];
            uv2 = g_uact [i2048 + DINNER];
            zv2 = g_xz   [i4096 + 2 * DINNER];
            Bv2 = g_xdbl [i96 + 96 + 64 + n];
            Cv2 = g_xdbl [i96 + 96 + 80 + n];
        }
        float dA = __expf(dv * Av);
        h = fmaf(dA, h, dv * Bv * uv);
        float p = h * Cv;
        p += __shfl_xor_sync(0xffffffffu, p, 8, 16);
        p += __shfl_xor_sync(0xffffffffu, p, 4, 16);
        p += __shfl_xor_sync(0xffffffffu, p, 2, 16);
        p += __shfl_xor_sync(0xffffffffu, p, 1, 16);
        if (n == 0) {
            float sil = zv / (1.f + __expf(-zv));
            g_yv[i2048] = (p + uv * Dv) * sil;
        }
        dv = dv2; uv = uv2; zv = zv2; Bv = Bv2; Cv = Cv2;
        i2048 += DINNER; i4096 += 2 * DINNER; i96 += 96;
    }
}

// ---------------- host launcher ----------------------------------------------
extern "C" void kernel_launch(void* const* d_in, const int* in_sizes, int n_in,
                              void* d_out, int out_size)
{
    (void)in_sizes; (void)n_in; (void)out_size;
    const float* x      = (const float*)d_in[0];
    const float* w_in   = (const float*)d_in[1];
    const float* conv_w = (const float*)d_in[2];
    const float* conv_b = (const float*)d_in[3];
    const float* w_x    = (const float*)d_in[4];
    const float* w_dt   = (const float*)d_in[5];
    const float* b_dt   = (const float*)d_in[6];
    const float* A_log  = (const float*)d_in[7];
    const float* Dp     = (const float*)d_in[8];
    const float* w_out  = (const float*)d_in[9];
    const float* w_p    = (const float*)d_in[10];
    const float* b_p    = (const float*)d_in[11];
    float* out = (float*)d_out;

    float *xt, *xz, *uact, *xdbl, *delta, *yv, *o1, *o2;
    cudaGetSymbolAddress((void**)&xt,    g_xt);
    cudaGetSymbolAddress((void**)&xz,    g_xz);
    cudaGetSymbolAddress((void**)&uact,  g_uact);
    cudaGetSymbolAddress((void**)&xdbl,  g_xdbl);
    cudaGetSymbolAddress((void**)&delta, g_delta);
    cudaGetSymbolAddress((void**)&yv,    g_yv);
    cudaGetSymbolAddress((void**)&o1,    g_o1);
    cudaGetSymbolAddress((void**)&o2,    g_o2);

    // 0) transpose x: (B, d_model, L) -> (B, L, d_model)
    transpose_k<<<dim3(L_SEQ / 32, DMODEL / 32, B_SZ), dim3(32, 8)>>>(
        x, xt, DMODEL, L_SEQ);

    // 1) in_proj: xz = xt @ w_in^T   [8192,1024] x [4096,1024]^T
    tgemm<0, false><<<dim3((2 * DINNER) / 128, MTOT / 128), 256>>>(
        xt, w_in, nullptr, xz, DMODEL, DMODEL, DMODEL, 2 * DINNER, 2 * DINNER);

    // 2) depthwise causal conv + silu -> uact
    conv_silu_k<<<(MTOT * DINNER) / 256, 256>>>(conv_w, conv_b);

    // 3) x_proj: xdbl = uact @ w_x^T  (N=96, guarded)
    tgemm<0, true><<<dim3(1, MTOT / 128), 256>>>(
        uact, w_x, nullptr, xdbl, DINNER, DINNER, DINNER, 96, 96);

    // 4) delta = softplus(xdbl[:, :64] @ w_dt^T + b_dt)  (K=64, lda=96)
    tgemm<2, false><<<dim3(DINNER / 128, MTOT / 128), 256>>>(
        xdbl, w_dt, b_dt, delta, 64, 96, 64, DINNER, DINNER);

    // 5) selective scan (fuses D-skip and silu(z) gate) -> yv
    scan_k<<<B_SZ * (DINNER / 16), 256>>>(A_log, Dp);

    // 6) out_proj: o1 = yv @ w_out^T
    tgemm<0, false><<<dim3(DMODEL / 128, MTOT / 128), 256>>>(
        yv, w_out, nullptr, o1, DINNER, DINNER, DINNER, DMODEL, DMODEL);

    // 7) proj: o2 = o1 @ w_p^T + b_p
    tgemm<1, false><<<dim3(DMODEL / 128, MTOT / 128), 256>>>(
        o1, w_p, b_p, o2, DMODEL, DMODEL, DMODEL, DMODEL, DMODEL);

    // 8) transpose to (B, d_model, L): o2 [b][l][m] -> out [b][m][l]
    transpose_k<<<dim3(DMODEL / 32, L_SEQ / 32, B_SZ), dim3(32, 8)>>>(
        o2, out, L_SEQ, DMODEL);
}

// round 3
// speedup vs baseline: 2.0940x; 1.0731x over previous
#include <cuda_runtime.h>
#include <math.h>
#include <stdint.h>

#define B_SZ   4
#define L_SEQ  2048
#define DMODEL 1024
#define DINNER 2048
#define DSTATE 16
#define MTOT   (B_SZ * L_SEQ)   // 8192

// ---------------- scratch ----------------------------------------------------
__device__ float g_xt   [(size_t)MTOT * DMODEL];        // x^T, tf32-rounded
__device__ float g_xz   [(size_t)MTOT * 2 * DINNER];    // in_proj out (u|z) exact
__device__ float g_uact [(size_t)MTOT * DINNER];        // conv+silu, rounded
__device__ float g_xdbl [(size_t)MTOT * 96];            // x_proj out, rounded
__device__ float g_part [(size_t)4 * MTOT * 96];        // split-K partials
__device__ float g_delta[(size_t)MTOT * DINNER];        // softplus(dt) exact
__device__ float g_yv   [(size_t)MTOT * DINNER];        // scan out, rounded
__device__ float g_o1   [(size_t)MTOT * DMODEL];        // rounded
__device__ float g_o2   [(size_t)MTOT * DMODEL];        // exact
__device__ float g_wr   [7667712];                      // all weights, rounded

#define WOFF_IN  0
#define WOFF_X   4194304
#define WOFF_DT  4390912
#define WOFF_OUT 4521984
#define WOFF_P   6619136

__device__ __forceinline__ uint32_t f2tf32(float f) {
    uint32_t r;
    asm("cvt.rna.tf32.f32 %0, %1;" : "=r"(r) : "f"(f));
    return r;
}
__device__ __forceinline__ float roundtf(float f) {
    return __uint_as_float(f2tf32(f));
}

__device__ __forceinline__ void cp16(uint32_t dst, const float* src, bool pred) {
    int sz = pred ? 16 : 0;
    asm volatile("cp.async.cg.shared.global [%0], [%1], 16, %2;\n"
                 :: "r"(dst), "l"(src), "r"(sz));
}

#define MMA_TF32(c, a, b)                                             \
    asm volatile(                                                     \
        "mma.sync.aligned.m16n8k8.row.col.f32.tf32.tf32.f32 "         \
        "{%0,%1,%2,%3}, {%4,%5,%6,%7}, {%8,%9}, {%0,%1,%2,%3};\n"     \
        : "+f"(c[0]), "+f"(c[1]), "+f"(c[2]), "+f"(c[3])              \
        : "r"(a[0]), "r"(a[1]), "r"(a[2]), "r"(a[3]),                 \
          "r"(b[0]), "r"(b[1]))

// ---------------- tf32 GEMM, cp.async 3-stage, C = A @ W^T -------------------
// A row-major [M, lda] (tf32-rounded), W row-major [N, ldb] (tf32-rounded).
// grid.z = split-K chunks: A,W advance by z*K in k; C advances by z*cz.
// ACT: 0 none, 1 +bias, 2 +bias+softplus.  ROUND: tf32-round output.
// smem/stage: A 128x20 + B 128x20 floats = 20480B; 3 stages = 61440B dynamic.
template<int ACT, bool NGUARD, bool ROUND>
__global__ void __launch_bounds__(256, 2)
tgemm(const float* __restrict__ A, const float* __restrict__ W,
      const float* __restrict__ bias, float* __restrict__ C,
      int K, int lda, int ldb, int ldc, int Nt, long cz)
{
    extern __shared__ float sm[];
    const int tid  = threadIdx.x;
    const int wid  = tid >> 5, lane = tid & 31;
    const int m0   = blockIdx.y * 128, n0 = blockIdx.x * 128;
    const int wm   = (wid & 1) * 64, wn = (wid >> 1) * 32;
    const int gid  = lane >> 2, tig = lane & 3;
    const int lr   = tid >> 2, lk = (tid & 3) * 4;

    A += (long)blockIdx.z * K;
    W += (long)blockIdx.z * K;
    C += (long)blockIdx.z * cz;

    const float* Ap0 = A + (long)(m0 + lr) * lda + lk;
    const float* Ap1 = Ap0 + (long)64 * lda;
    const bool bok0 = !NGUARD || (n0 + lr)      < Nt;
    const bool bok1 = !NGUARD || (n0 + lr + 64) < Nt;
    const float* Bp0 = W + (long)(n0 + lr) * ldb + lk;
    const float* Bp1 = Bp0 + (long)64 * ldb;

    const uint32_t sb = (uint32_t)__cvta_generic_to_shared(sm);
    const uint32_t dA0 = sb + (uint32_t)(lr * 20 + lk) * 4;
    const uint32_t dA1 = sb + (uint32_t)((lr + 64) * 20 + lk) * 4;
    const uint32_t dB0 = sb + (uint32_t)(2560 + lr * 20 + lk) * 4;
    const uint32_t dB1 = sb + (uint32_t)(2560 + (lr + 64) * 20 + lk) * 4;

    const int nk = K / 16;

    // prologue: stages 0,1
    cp16(dA0, Ap0, true);  cp16(dA1, Ap1, true);
    cp16(dB0, Bp0, bok0);  cp16(dB1, Bp1, bok1);
    asm volatile("cp.async.commit_group;\n");
    if (nk > 1) {
        cp16(dA0 + 20480, Ap0 + 16, true);  cp16(dA1 + 20480, Ap1 + 16, true);
        cp16(dB0 + 20480, Bp0 + 16, bok0);  cp16(dB1 + 20480, Bp1 + 16, bok1);
    }
    asm volatile("cp.async.commit_group;\n");

    float acc[4][4][4];
#pragma unroll
    for (int i = 0; i < 4; i++)
#pragma unroll
        for (int j = 0; j < 4; j++)
#pragma unroll
            for (int q = 0; q < 4; q++) acc[i][j][q] = 0.f;

    for (int kt = 0; kt < nk; kt++) {
        asm volatile("cp.async.wait_group 1;\n" ::: "memory");
        __syncthreads();

        if (kt + 2 < nk) {
            const uint32_t so = (uint32_t)((kt + 2) % 3) * 20480u;
            const int ko = (kt + 2) * 16;
            cp16(dA0 + so, Ap0 + ko, true);  cp16(dA1 + so, Ap1 + ko, true);
            cp16(dB0 + so, Bp0 + ko, bok0);  cp16(dB1 + so, Bp1 + ko, bok1);
        }
        asm volatile("cp.async.commit_group;\n");

        const uint32_t* Asu = (const uint32_t*)(sm + (kt % 3) * 5120);
        const uint32_t* Bsu = Asu + 2560;

#pragma unroll
        for (int ks = 0; ks < 2; ks++) {
            const int kb = ks * 8 + tig;
            uint32_t af[4][4], bf[4][2];
#pragma unroll
            for (int mi = 0; mi < 4; mi++) {
                const uint32_t* p = &Asu[(wm + mi * 16 + gid) * 20 + kb];
                af[mi][0] = p[0];
                af[mi][1] = p[8 * 20];
                af[mi][2] = p[4];
                af[mi][3] = p[8 * 20 + 4];
            }
#pragma unroll
            for (int ni = 0; ni < 4; ni++) {
                const uint32_t* p = &Bsu[(wn + ni * 8 + gid) * 20 + kb];
                bf[ni][0] = p[0];
                bf[ni][1] = p[4];
            }
#pragma unroll
            for (int mi = 0; mi < 4; mi++)
#pragma unroll
                for (int ni = 0; ni < 4; ni++)
                    MMA_TF32(acc[mi][ni], af[mi], bf[ni]);
        }
        __syncthreads();
    }

#pragma unroll
    for (int mi = 0; mi < 4; mi++) {
        const int r0 = m0 + wm + mi * 16 + gid;
        const int r1 = r0 + 8;
#pragma unroll
        for (int ni = 0; ni < 4; ni++) {
            const int cn = n0 + wn + ni * 8 + tig * 2;
            if (NGUARD && cn >= Nt) continue;
            float v0 = acc[mi][ni][0], v1 = acc[mi][ni][1];
            float v2 = acc[mi][ni][2], v3 = acc[mi][ni][3];
            if (ACT >= 1) {
                const float b0 = bias[cn], b1 = bias[cn + 1];
                v0 += b0; v1 += b1; v2 += b0; v3 += b1;
            }
            if (ACT == 2) {
                v0 = (v0 > 20.f) ? v0 : log1pf(__expf(v0));
                v1 = (v1 > 20.f) ? v1 : log1pf(__expf(v1));
                v2 = (v2 > 20.f) ? v2 : log1pf(__expf(v2));
                v3 = (v3 > 20.f) ? v3 : log1pf(__expf(v3));
            }
            if (ROUND) {
                v0 = roundtf(v0); v1 = roundtf(v1);
                v2 = roundtf(v2); v3 = roundtf(v3);
            }
            C[(long)r0 * ldc + cn]     = v0;
            C[(long)r0 * ldc + cn + 1] = v1;
            C[(long)r1 * ldc + cn]     = v2;
            C[(long)r1 * ldc + cn + 1] = v3;
        }
    }
}

// ---------------- weight rounding (all 5 weight mats -> g_wr) ----------------
__global__ void round_w_k(const float* __restrict__ w_in, const float* __restrict__ w_x,
                          const float* __restrict__ w_dt, const float* __restrict__ w_out,
                          const float* __restrict__ w_p)
{
    const long i4 = ((long)blockIdx.x * 256 + threadIdx.x) * 4;
    if (i4 >= 7667712) return;
    const float* src;
    long off;
    if      (i4 < WOFF_X)   { src = w_in;  off = i4 - WOFF_IN;  }
    else if (i4 < WOFF_DT)  { src = w_x;   off = i4 - WOFF_X;   }
    else if (i4 < WOFF_OUT) { src = w_dt;  off = i4 - WOFF_DT;  }
    else if (i4 < WOFF_P)   { src = w_out; off = i4 - WOFF_OUT; }
    else                    { src = w_p;   off = i4 - WOFF_P;   }
    float4 v = *(const float4*)(src + off);
    v.x = roundtf(v.x); v.y = roundtf(v.y); v.z = roundtf(v.z); v.w = roundtf(v.w);
    *(float4*)(g_wr + i4) = v;
}

// ---------------- 32x32 tiled transpose: dst[z][c][r] = src[z][r][c] ---------
template<bool R>
__global__ void transpose_k(const float* __restrict__ src, float* __restrict__ dst,
                            int Rr, int Cc)
{
    __shared__ float t[32][33];
    const long zoff = (long)blockIdx.z * Rr * Cc;
    const float* s = src + zoff;
    float* d = dst + zoff;
    const int r0 = blockIdx.y * 32, c0 = blockIdx.x * 32;
#pragma unroll
    for (int i = threadIdx.y; i < 32; i += 8)
        t[i][threadIdx.x] = s[(long)(r0 + i) * Cc + c0 + threadIdx.x];
    __syncthreads();
#pragma unroll
    for (int i = threadIdx.y; i < 32; i += 8) {
        float v = t[threadIdx.x][i];
        if (R) v = roundtf(v);
        d[(long)(c0 + i) * Rr + r0 + threadIdx.x] = v;
    }
}

// ---------------- depthwise causal conv(4) + SiLU (rounded out) --------------
__global__ void __launch_bounds__(256)
conv_silu_k(const float* __restrict__ cw, const float* __restrict__ cb)
{
    long idx = (long)blockIdx.x * 256 + threadIdx.x;
    int  e  = (int)(idx % DINNER);
    long bl = idx / DINNER;
    int  l  = (int)(bl % L_SEQ);
    long brow = bl - l;
    float acc = cb[e];
#pragma unroll
    for (int k = 0; k < 4; k++) {
        int t = l - 3 + k;
        if (t >= 0)
            acc = fmaf(cw[e * 4 + k], g_xz[(brow + t) * (2 * DINNER) + e], acc);
    }
    float s = acc / (1.f + __expf(-acc));
    g_uact[idx] = roundtf(s);
}

// ---------------- split-K reduce for x_proj (round output) -------------------
__global__ void reduce4_k()
{
    const long i = (long)blockIdx.x * 256 + threadIdx.x;   // over 8192*96
    const long S = (long)MTOT * 96;
    float v = g_part[i] + g_part[i + S] + g_part[i + 2 * S] + g_part[i + 3 * S];
    g_xdbl[i] = roundtf(v);
}

// ---------------- selective scan (fuses D-skip + silu(z) gate) ---------------
__global__ void __launch_bounds__(256)
scan_k(const float* __restrict__ A_log, const float* __restrict__ Dp)
{
    const int b  = blockIdx.x >> 7;
    const int dg = blockIdx.x & 127;
    const int ci = threadIdx.x >> 4;
    const int n  = threadIdx.x & 15;
    const int d  = dg * 16 + ci;

    const float Av = -expf(A_log[d * DSTATE + n]);
    const float Dv = Dp[d];

    long i2048 = ((long)b * L_SEQ) * DINNER + d;
    long i4096 = ((long)b * L_SEQ) * (2 * DINNER) + DINNER + d;
    long i96   = ((long)b * L_SEQ) * 96;

    float h  = 0.f;
    float dv = g_delta[i2048];
    float uv = g_uact[i2048];
    float zv = g_xz[i4096];
    float Bv = g_xdbl[i96 + 64 + n];
    float Cv = g_xdbl[i96 + 80 + n];

    for (int l = 0; l < L_SEQ; l++) {
        float dv2 = 0.f, uv2 = 0.f, zv2 = 0.f, Bv2 = 0.f, Cv2 = 0.f;
        if (l + 1 < L_SEQ) {
            dv2 = g_delta[i2048 + DINNER];
            uv2 = g_uact [i2048 + DINNER];
            zv2 = g_xz   [i4096 + 2 * DINNER];
            Bv2 = g_xdbl [i96 + 96 + 64 + n];
            Cv2 = g_xdbl [i96 + 96 + 80 + n];
        }
        float dA = __expf(dv * Av);
        h = fmaf(dA, h, dv * Bv * uv);
        float p = h * Cv;
        p += __shfl_xor_sync(0xffffffffu, p, 8, 16);
        p += __shfl_xor_sync(0xffffffffu, p, 4, 16);
        p += __shfl_xor_sync(0xffffffffu, p, 2, 16);
        p += __shfl_xor_sync(0xffffffffu, p, 1, 16);
        if (n == 0) {
            float sil = zv / (1.f + __expf(-zv));
            g_yv[i2048] = roundtf((p + uv * Dv) * sil);
        }
        dv = dv2; uv = uv2; zv = zv2; Bv = Bv2; Cv = Cv2;
        i2048 += DINNER; i4096 += 2 * DINNER; i96 += 96;
    }
}

// ---------------- host launcher ----------------------------------------------
#define SMEM_T 61440

extern "C" void kernel_launch(void* const* d_in, const int* in_sizes, int n_in,
                              void* d_out, int out_size)
{
    (void)in_sizes; (void)n_in; (void)out_size;
    const float* x      = (const float*)d_in[0];
    const float* w_in   = (const float*)d_in[1];
    const float* conv_w = (const float*)d_in[2];
    const float* conv_b = (const float*)d_in[3];
    const float* w_x    = (const float*)d_in[4];
    const float* w_dt   = (const float*)d_in[5];
    const float* b_dt   = (const float*)d_in[6];
    const float* A_log  = (const float*)d_in[7];
    const float* Dp     = (const float*)d_in[8];
    const float* w_out  = (const float*)d_in[9];
    const float* w_p    = (const float*)d_in[10];
    const float* b_p    = (const float*)d_in[11];
    float* out = (float*)d_out;

    float *xt, *xz, *uact, *xdbl, *part, *delta, *yv, *o1, *o2, *wr;
    cudaGetSymbolAddress((void**)&xt,    g_xt);
    cudaGetSymbolAddress((void**)&xz,    g_xz);
    cudaGetSymbolAddress((void**)&uact,  g_uact);
    cudaGetSymbolAddress((void**)&xdbl,  g_xdbl);
    cudaGetSymbolAddress((void**)&part,  g_part);
    cudaGetSymbolAddress((void**)&delta, g_delta);
    cudaGetSymbolAddress((void**)&yv,    g_yv);
    cudaGetSymbolAddress((void**)&o1,    g_o1);
    cudaGetSymbolAddress((void**)&o2,    g_o2);
    cudaGetSymbolAddress((void**)&wr,    g_wr);

    cudaFuncSetAttribute(tgemm<0,false,false>, cudaFuncAttributeMaxDynamicSharedMemorySize, SMEM_T);
    cudaFuncSetAttribute(tgemm<0,true, false>, cudaFuncAttributeMaxDynamicSharedMemorySize, SMEM_T);
    cudaFuncSetAttribute(tgemm<2,false,false>, cudaFuncAttributeMaxDynamicSharedMemorySize, SMEM_T);
    cudaFuncSetAttribute(tgemm<0,false,true >, cudaFuncAttributeMaxDynamicSharedMemorySize, SMEM_T);
    cudaFuncSetAttribute(tgemm<1,false,false>, cudaFuncAttributeMaxDynamicSharedMemorySize, SMEM_T);

    // 0) round all weights into g_wr
    round_w_k<<<(7667712 / 4 + 255) / 256, 256>>>(w_in, w_x, w_dt, w_out, w_p);

    // 0b) transpose x: (B, d_model, L) -> (B, L, d_model), tf32-rounded
    transpose_k<true><<<dim3(L_SEQ / 32, DMODEL / 32, B_SZ), dim3(32, 8)>>>(
        x, xt, DMODEL, L_SEQ);

    // 1) in_proj: xz = xt @ w_in^T
    tgemm<0,false,false><<<dim3(32, 64, 1), 256, SMEM_T>>>(
        xt, wr + WOFF_IN, nullptr, xz, DMODEL, DMODEL, DMODEL, 2 * DINNER, 0, 0);

    // 2) conv + silu -> uact (rounded)
    conv_silu_k<<<((long)MTOT * DINNER) / 256, 256>>>(conv_w, conv_b);

    // 3) x_proj split-K x4: partials then reduce (rounded)
    tgemm<0,true,false><<<dim3(1, 64, 4), 256, SMEM_T>>>(
        uact, wr + WOFF_X, nullptr, part, 512, DINNER, DINNER, 96, 96,
        (long)MTOT * 96);
    reduce4_k<<<((long)MTOT * 96) / 256, 256>>>();

    // 4) delta = softplus(xdbl[:, :64] @ w_dt^T + b_dt)
    tgemm<2,false,false><<<dim3(16, 64, 1), 256, SMEM_T>>>(
        xdbl, wr + WOFF_DT, b_dt, delta, 64, 96, 64, DINNER, 0, 0);

    // 5) selective scan -> yv (rounded)
    scan_k<<<B_SZ * (DINNER / 16), 256>>>(A_log, Dp);

    // 6) out_proj: o1 = yv @ w_out^T (rounded)
    tgemm<0,false,true><<<dim3(8, 64, 1), 256, SMEM_T>>>(
        yv, wr + WOFF_OUT, nullptr, o1, DINNER, DINNER, DINNER, DMODEL, 0, 0);

    // 7) proj: o2 = o1 @ w_p^T + b_p
    tgemm<1,false,false><<<dim3(8, 64, 1), 256, SMEM_T>>>(
        o1, wr + WOFF_P, b_p, o2, DMODEL, DMODEL, DMODEL, DMODEL, 0, 0);

    // 8) transpose to (B, d_model, L)
    transpose_k<false><<<dim3(DMODEL / 32, L_SEQ / 32, B_SZ), dim3(32, 8)>>>(
        o2, out, L_SEQ, DMODEL);
}